// round 2
// baseline (speedup 1.0000x reference)
#include <cuda_runtime.h>
#include <cuda_bf16.h>
#include <cstdint>

#define B_  4
#define S_  4096
#define D_  1024
#define M_  (B_ * S_)          // 16384 rows
#define NPROJ 5120             // 1024 (a) + 1024 (o) + 2048 (B) + 1024 (dt)
#define EPS 1e-6f

// ---------------- scratch (static device globals; no allocation) ------------
__device__ float  g_P[(size_t)M_ * NPROJ];     // projections (335 MB)
__device__ float4 g_T[(size_t)M_ * D_];        // (a, b, u0, u1) packed (268 MB)
__device__ float  g_H[(size_t)M_ * 2 * D_];    // states, row-major (m, 2d+j)

// ---------------- generic fp32 tiled GEMM:  C = A @ B + bias ----------------
// A: Mdim x Kdim (lda), B: Kdim x Ndim (ldb), C: Mdim x Ndim (ldc)
// BM=BN=128, BK=16, 256 threads, 8x8 per-thread tile.
__global__ __launch_bounds__(256) void sgemm_bias(
    const float* __restrict__ A, const float* __restrict__ Bm,
    const float* __restrict__ bias, float* __restrict__ C,
    int Kdim, int lda, int ldb, int ldc)
{
    __shared__ float As[16][128];
    __shared__ float Bs[16][128];

    const int bm = blockIdx.y * 128;
    const int bn = blockIdx.x * 128;
    const int tid = threadIdx.x;
    const int tm = (tid >> 4) * 8;     // 0..120
    const int tn = (tid & 15) * 8;     // 0..120

    float acc[8][8];
#pragma unroll
    for (int i = 0; i < 8; i++)
#pragma unroll
        for (int j = 0; j < 8; j++) acc[i][j] = 0.f;

    const int ar = tid >> 2;           // 0..63
    const int ac = (tid & 3) * 4;      // 0,4,8,12
    const int br = tid >> 5;           // 0..7
    const int bc = (tid & 31) * 4;     // 0..124

    for (int k0 = 0; k0 < Kdim; k0 += 16) {
        // load A tile (128x16) transposed into As[k][m]
#pragma unroll
        for (int i = 0; i < 2; i++) {
            int r = ar + i * 64;
            float4 v = *(const float4*)&A[(size_t)(bm + r) * lda + k0 + ac];
            As[ac + 0][r] = v.x;
            As[ac + 1][r] = v.y;
            As[ac + 2][r] = v.z;
            As[ac + 3][r] = v.w;
        }
        // load B tile (16x128)
#pragma unroll
        for (int i = 0; i < 2; i++) {
            int r = br + i * 8;
            float4 v = *(const float4*)&Bm[(size_t)(k0 + r) * ldb + bn + bc];
            *(float4*)&Bs[r][bc] = v;
        }
        __syncthreads();

#pragma unroll
        for (int kk = 0; kk < 16; kk++) {
            float af[8], bf[8];
#pragma unroll
            for (int i = 0; i < 8; i++) af[i] = As[kk][tm + i];
#pragma unroll
            for (int j = 0; j < 8; j++) bf[j] = Bs[kk][tn + j];
#pragma unroll
            for (int i = 0; i < 8; i++)
#pragma unroll
                for (int j = 0; j < 8; j++)
                    acc[i][j] = fmaf(af[i], bf[j], acc[i][j]);
        }
        __syncthreads();
    }

#pragma unroll
    for (int j4 = 0; j4 < 8; j4 += 4) {
        float4 bv = *(const float4*)&bias[bn + tn + j4];
#pragma unroll
        for (int i = 0; i < 8; i++) {
            float4 v;
            v.x = acc[i][j4 + 0] + bv.x;
            v.y = acc[i][j4 + 1] + bv.y;
            v.z = acc[i][j4 + 2] + bv.z;
            v.w = acc[i][j4 + 3] + bv.w;
            *(float4*)&C[(size_t)(bm + tm + i) * ldc + bn + tn + j4] = v;
        }
    }
}

// ---------------- elementwise transform -------------------------------------
__device__ __forceinline__ float softplus_f(float x) {
    // softplus(x) = max(x,0) + log1p(exp(-|x|))
    return fmaxf(x, 0.f) + log1pf(expf(-fabsf(x)));
}

__global__ __launch_bounds__(256) void k_elem(const float* __restrict__ x)
{
    size_t idx = (size_t)blockIdx.x * blockDim.x + threadIdx.x;  // m*D + d
    if (idx >= (size_t)M_ * D_) return;
    int d = (int)(idx & (D_ - 1));
    size_t m = idx >> 10;

    const float* Prow = g_P + m * NPROJ;
    float alpha = softplus_f(Prow[d]);
    float omega = Prow[1024 + d];
    float2 Bv   = ((const float2*)(Prow + 2048))[d];
    float dt    = softplus_f(Prow[4096 + d]);

    float xv  = x[idx];
    float tau = dt * 0.5f;
    float opa = fmaf(tau, alpha, 1.0f);
    float tw  = tau * omega;
    float inv = 1.0f / (fmaf(opa, opa, fmaf(tw, tw, EPS)));
    float m11 = opa * inv;
    float m12 = tw * inv;
    float oma = fmaf(-tau, alpha, 1.0f);

    float a = m11 * oma - m12 * tw;    // a11 == a22
    float b = m11 * tw + m12 * oma;    // a12 == -a21

    float Bx0 = Bv.x * xv;
    float Bx1 = Bv.y * xv;
    float u0 = dt * (fmaf(m11, Bx0,  m12 * Bx1));
    float u1 = dt * (fmaf(-m12, Bx0, m11 * Bx1));

    g_T[idx] = make_float4(a, b, u0, u1);
}

// ---------------- sequential scan over S ------------------------------------
// one thread per (b, d): h1' = a*h1 + b*h2 + u0 ; h2' = -b*h1 + a*h2 + u1
__global__ __launch_bounds__(128) void k_scan(const float* __restrict__ state,
                                              float* __restrict__ out_fs)
{
    int gid = blockIdx.x * blockDim.x + threadIdx.x;   // 0..4095
    int b = gid >> 10;
    int d = gid & (D_ - 1);

    float h1 = state[(size_t)(b * D_ + d) * 2 + 0];
    float h2 = state[(size_t)(b * D_ + d) * 2 + 1];

    size_t base = (size_t)b * S_ * D_ + d;
    float2* Hout = (float2*)g_H;   // index m*D_ + d -> (h1, h2)

#pragma unroll 8
    for (int s = 0; s < S_; s++) {
        size_t i = base + (size_t)s * D_;
        float4 t = g_T[i];
        float nh1 = fmaf(t.x, h1, fmaf( t.y, h2, t.z));
        float nh2 = fmaf(t.x, h2, fmaf(-t.y, h1, t.w));
        h1 = nh1; h2 = nh2;
        Hout[i] = make_float2(h1, h2);
    }
    if (out_fs) {
        out_fs[(size_t)(b * D_ + d) * 2 + 0] = h1;
        out_fs[(size_t)(b * D_ + d) * 2 + 1] = h2;
    }
}

// ---------------- launcher ---------------------------------------------------
extern "C" void kernel_launch(void* const* d_in, const int* in_sizes, int n_in,
                              void* d_out, int out_size)
{
    const float* x     = (const float*)d_in[0];
    const float* state = (const float*)d_in[1];
    const float* Wa    = (const float*)d_in[2];
    const float* ba    = (const float*)d_in[3];
    const float* Wo    = (const float*)d_in[4];
    const float* bo    = (const float*)d_in[5];
    const float* WB    = (const float*)d_in[6];
    const float* bB    = (const float*)d_in[7];
    const float* Wdt   = (const float*)d_in[8];

    const float *WC, *bC, *bdt;
    if (in_sizes[9] == 1024) {        // signature order: ..., Wdt, bdt, WC, bC
        bdt = (const float*)d_in[9];
        WC  = (const float*)d_in[10];
        bC  = (const float*)d_in[11];
    } else {                           // dict order: ..., Wdt, WC, bC, bdt
        WC  = (const float*)d_in[9];
        bC  = (const float*)d_in[10];
        bdt = (const float*)d_in[11];
    }

    float* out = (float*)d_out;
    float* out_fs = nullptr;
    if (out_size >= (int)((size_t)M_ * D_ + (size_t)B_ * D_ * 2))
        out_fs = out + (size_t)M_ * D_;

    float *pP, *pH;
    cudaGetSymbolAddress((void**)&pP, g_P);
    cudaGetSymbolAddress((void**)&pH, g_H);

    dim3 blk(256);

    // 4 projection GEMMs into g_P columns [0,1024) [1024,2048) [2048,4096) [4096,5120)
    sgemm_bias<<<dim3(1024 / 128, M_ / 128), blk>>>(x, Wa,  ba,  pP + 0,    D_, D_, D_,     NPROJ);
    sgemm_bias<<<dim3(1024 / 128, M_ / 128), blk>>>(x, Wo,  bo,  pP + 1024, D_, D_, D_,     NPROJ);
    sgemm_bias<<<dim3(2048 / 128, M_ / 128), blk>>>(x, WB,  bB,  pP + 2048, D_, D_, 2 * D_, NPROJ);
    sgemm_bias<<<dim3(1024 / 128, M_ / 128), blk>>>(x, Wdt, bdt, pP + 4096, D_, D_, D_,     NPROJ);

    // elementwise -> packed (a, b, u0, u1)
    k_elem<<<(unsigned)(((size_t)M_ * D_ + 255) / 256), blk>>>(x);

    // sequential scan (4096 independent lanes)
    k_scan<<<32, 128>>>(state, out_fs);

    // output GEMM: g_H (16384 x 2048) @ WC (2048 x 1024) + bC
    sgemm_bias<<<dim3(1024 / 128, M_ / 128), blk>>>(pH, WC, bC, out, 2 * D_, 2 * D_, D_, D_);
}

// round 8
// speedup vs baseline: 2.9420x; 2.9420x over previous
#include <cuda_runtime.h>
#include <cuda_bf16.h>
#include <cstdint>

#define B_  4
#define S_  4096
#define D_  1024
#define M_  (B_ * S_)          // 16384 rows
#define NPROJ 5120             // 1024(a)+1024(o)+2048(B)+1024(dt)
#define EPS 1e-6f

#define CH_ 16                 // scan chunks
#define CL_ (S_ / CH_)         // 256 steps per chunk

// ---------------- scratch (static device globals; no allocation) ------------
__device__ float  g_P[(size_t)M_ * NPROJ];          // projections (335MB)
__device__ float4 g_T[(size_t)M_ * D_];             // (a,b,u0,u1) (268MB)
__device__ __nv_bfloat16 g_xhi[(size_t)M_ * D_];
__device__ __nv_bfloat16 g_xlo[(size_t)M_ * D_];
__device__ __nv_bfloat16 g_Wthi[(size_t)NPROJ * D_];   // W^T concat, [n][k]
__device__ __nv_bfloat16 g_Wtlo[(size_t)NPROJ * D_];
__device__ __nv_bfloat16 g_WCthi[(size_t)D_ * 2 * D_]; // WC^T, [n=1024][k=2048]
__device__ __nv_bfloat16 g_WCtlo[(size_t)D_ * 2 * D_];
__device__ __nv_bfloat16 g_Hhi[(size_t)M_ * 2 * D_];   // states bf16 hi [m][2d+j]
__device__ __nv_bfloat16 g_Hlo[(size_t)M_ * 2 * D_];
__device__ float  g_biasP[NPROJ];
__device__ float4 g_CM[B_ * D_ * CH_];              // per-chunk (Mr,Mi,Er,Ei)
__device__ float2 g_HIN[B_ * D_ * CH_];             // per-chunk entry state

// ======================= PTX helpers =========================================
__device__ __forceinline__ uint32_t smem_u32(const void* p) {
    uint32_t a;
    asm("{ .reg .u64 t; cvta.to.shared.u64 t, %1; cvt.u32.u64 %0, t; }" : "=r"(a) : "l"(p));
    return a;
}
__device__ __forceinline__ void cp_async16(uint32_t s, const void* g) {
    asm volatile("cp.async.cg.shared.global [%0], [%1], 16;" :: "r"(s), "l"(g));
}
#define CP_COMMIT()  asm volatile("cp.async.commit_group;" ::: "memory")
#define CP_WAIT1()   asm volatile("cp.async.wait_group 1;" ::: "memory")
#define CP_WAIT0()   asm volatile("cp.async.wait_group 0;" ::: "memory")

__device__ __forceinline__ void ldsm_x4(uint32_t& r0, uint32_t& r1, uint32_t& r2,
                                        uint32_t& r3, uint32_t addr) {
    asm volatile("ldmatrix.sync.aligned.m8n8.x4.shared.b16 {%0,%1,%2,%3}, [%4];"
                 : "=r"(r0), "=r"(r1), "=r"(r2), "=r"(r3) : "r"(addr));
}
__device__ __forceinline__ void mma_bf16(float* c, const uint32_t* a, const uint32_t* b) {
    asm volatile(
        "mma.sync.aligned.m16n8k16.row.col.f32.bf16.bf16.f32 "
        "{%0,%1,%2,%3}, {%4,%5,%6,%7}, {%8,%9}, {%0,%1,%2,%3};"
        : "+f"(c[0]), "+f"(c[1]), "+f"(c[2]), "+f"(c[3])
        : "r"(a[0]), "r"(a[1]), "r"(a[2]), "r"(a[3]), "r"(b[0]), "r"(b[1]));
}

// ======================= bf16x3 GEMM (mma.sync, sm_100-safe) =================
// C[128 x 128] per CTA = A[128 x K] @ B^T where B is [N][K] row-major (= W^T).
// bf16 hi/lo split x3: Ahi*Bhi + Ahi*Blo + Alo*Bhi, fp32 accum.
// k-chunk 32, 3-stage cp.async pipeline. Rows padded 64B->80B (conflict-free
// ldmatrix: 8 consecutive rows at 80B stride touch 8 distinct 16B groups).
#define KC      32
#define ROWB    80                         // bytes per smem row (64 data + 16 pad)
#define TILE_BYTES (128 * ROWB)            // 10240
#define STAGE_BYTES (4 * TILE_BYTES)       // Ahi,Alo,Bhi,Blo = 40960
#define NSTAGE  3
#define GEMM_SMEM (NSTAGE * STAGE_BYTES)   // 122880

__global__ __launch_bounds__(256, 1) void gemm_bf16x3(
    const __nv_bfloat16* __restrict__ Ahi, const __nv_bfloat16* __restrict__ Alo,
    const __nv_bfloat16* __restrict__ Bhi, const __nv_bfloat16* __restrict__ Blo,
    const float* __restrict__ bias, float* __restrict__ C,
    int Kdim, int ldc)
{
    extern __shared__ char smem[];
    const uint32_t sbase = smem_u32(smem);

    const int tid  = threadIdx.x;
    const int wid  = tid >> 5;
    const int lane = tid & 31;
    const int bm   = blockIdx.y * 128;
    const int bn   = blockIdx.x * 128;
    const int wm   = (wid & 1) * 64;       // warp m offset
    const int wn   = (wid >> 1) * 32;      // warp n offset

    const size_t ldab = (size_t)Kdim * 2;  // bytes per row of A/B sources

    // cp.async: 8 chunks/thread/stage (2 per matrix). chunk c: row=c>>2, k16B=c&3
    const int c0 = tid, c1 = tid + 256;
    const int r0g = c0 >> 2, k0g = (c0 & 3) * 16;
    const int r1g = c1 >> 2, k1g = (c1 & 3) * 16;
    const uint32_t s0 = (uint32_t)(r0g * ROWB + k0g);
    const uint32_t s1 = (uint32_t)(r1g * ROWB + k1g);

    auto issue_stage = [&](int kc, int st) {
        const uint32_t sb = sbase + st * STAGE_BYTES;
        const size_t kbyte = (size_t)kc * (KC * 2);
        const size_t ga0 = (size_t)(bm + r0g) * ldab + kbyte + k0g;
        const size_t ga1 = (size_t)(bm + r1g) * ldab + kbyte + k1g;
        const size_t gb0 = (size_t)(bn + r0g) * ldab + kbyte + k0g;
        const size_t gb1 = (size_t)(bn + r1g) * ldab + kbyte + k1g;
        cp_async16(sb + s0,                  (const char*)Ahi + ga0);
        cp_async16(sb + s1,                  (const char*)Ahi + ga1);
        cp_async16(sb + TILE_BYTES + s0,     (const char*)Alo + ga0);
        cp_async16(sb + TILE_BYTES + s1,     (const char*)Alo + ga1);
        cp_async16(sb + 2 * TILE_BYTES + s0, (const char*)Bhi + gb0);
        cp_async16(sb + 2 * TILE_BYTES + s1, (const char*)Bhi + gb1);
        cp_async16(sb + 3 * TILE_BYTES + s0, (const char*)Blo + gb0);
        cp_async16(sb + 3 * TILE_BYTES + s1, (const char*)Blo + gb1);
        CP_COMMIT();
    };

    const int NC = Kdim / KC;
    issue_stage(0, 0);
    issue_stage(1, 1);

    float acc[4][4][4];
#pragma unroll
    for (int mt = 0; mt < 4; mt++)
#pragma unroll
        for (int nt = 0; nt < 4; nt++)
#pragma unroll
            for (int j = 0; j < 4; j++) acc[mt][nt][j] = 0.f;

    // ldmatrix lane offsets
    const int a_m = (lane & 7) + (lane & 8);          // row within m16 tile group
    const int a_k = (lane & 16) ? 8 : 0;              // k-half
    const int b_n = (lane & 7) + ((lane & 16) ? 8 : 0);
    const int b_k = (lane & 8) ? 8 : 0;

    for (int c = 0; c < NC; c++) {
        const int st = c % NSTAGE;
        if (c + 2 < NC) CP_WAIT1(); else CP_WAIT0();
        __syncthreads();

        const uint32_t sA_h = sbase + st * STAGE_BYTES;
        const uint32_t sA_l = sA_h + TILE_BYTES;
        const uint32_t sB_h = sA_h + 2 * TILE_BYTES;
        const uint32_t sB_l = sA_h + 3 * TILE_BYTES;

#pragma unroll
        for (int k16 = 0; k16 < KC / 16; k16++) {
            const int k0 = k16 * 16;
            uint32_t ah[4][4], al[4][4], bh[4][2], bl[4][2];
#pragma unroll
            for (int mt = 0; mt < 4; mt++) {
                uint32_t off = (uint32_t)((wm + mt * 16 + a_m) * ROWB + (k0 + a_k) * 2);
                ldsm_x4(ah[mt][0], ah[mt][1], ah[mt][2], ah[mt][3], sA_h + off);
                ldsm_x4(al[mt][0], al[mt][1], al[mt][2], al[mt][3], sA_l + off);
            }
#pragma unroll
            for (int np = 0; np < 2; np++) {
                uint32_t off = (uint32_t)((wn + np * 16 + b_n) * ROWB + (k0 + b_k) * 2);
                ldsm_x4(bh[2*np][0], bh[2*np][1], bh[2*np+1][0], bh[2*np+1][1], sB_h + off);
                ldsm_x4(bl[2*np][0], bl[2*np][1], bl[2*np+1][0], bl[2*np+1][1], sB_l + off);
            }
#pragma unroll
            for (int mt = 0; mt < 4; mt++)
#pragma unroll
                for (int nt = 0; nt < 4; nt++) {
                    mma_bf16(acc[mt][nt], ah[mt], bh[nt]);
                    mma_bf16(acc[mt][nt], ah[mt], bl[nt]);
                    mma_bf16(acc[mt][nt], al[mt], bh[nt]);
                }
        }
        __syncthreads();
        if (c + 2 < NC) issue_stage(c + 2, (c + 2) % NSTAGE);
    }

    // epilogue: thread holds rows lane/4 (+8), cols 2*(lane%4) (+1) per tile
    const int er = lane >> 2;
    const int ec = (lane & 3) * 2;
#pragma unroll
    for (int mt = 0; mt < 4; mt++) {
#pragma unroll
        for (int nt = 0; nt < 4; nt++) {
            const int col = bn + wn + nt * 8 + ec;
            const float2 bv = *(const float2*)&bias[col];
            const int row0 = bm + wm + mt * 16 + er;
            float2 v0, v1;
            v0.x = acc[mt][nt][0] + bv.x;
            v0.y = acc[mt][nt][1] + bv.y;
            v1.x = acc[mt][nt][2] + bv.x;
            v1.y = acc[mt][nt][3] + bv.y;
            *(float2*)&C[(size_t)row0 * ldc + col]       = v0;
            *(float2*)&C[(size_t)(row0 + 8) * ldc + col] = v1;
        }
    }
}

// ======================= prep kernels ========================================
__device__ __forceinline__ void split_bf16(float v, __nv_bfloat16& h, __nv_bfloat16& l) {
    h = __float2bfloat16(v);
    l = __float2bfloat16(v - __bfloat162float(h));
}

__global__ __launch_bounds__(256) void k_split_x(const float* __restrict__ x) {
    size_t i4 = ((size_t)blockIdx.x * blockDim.x + threadIdx.x) * 4;
    if (i4 >= (size_t)M_ * D_) return;
    float4 v = *(const float4*)&x[i4];
    __nv_bfloat16 h0, l0, h1, l1, h2, l2, h3, l3;
    split_bf16(v.x, h0, l0); split_bf16(v.y, h1, l1);
    split_bf16(v.z, h2, l2); split_bf16(v.w, h3, l3);
    *(__nv_bfloat162*)&g_xhi[i4]     = __nv_bfloat162(h0, h1);
    *(__nv_bfloat162*)&g_xhi[i4 + 2] = __nv_bfloat162(h2, h3);
    *(__nv_bfloat162*)&g_xlo[i4]     = __nv_bfloat162(l0, l1);
    *(__nv_bfloat162*)&g_xlo[i4 + 2] = __nv_bfloat162(l2, l3);
}

// Wt_all[n][k]: n<1024 Wa; <2048 Wo; <4096 WB; <5120 Wdt (transposed reads)
__global__ __launch_bounds__(256) void k_build_wt(
    const float* __restrict__ Wa, const float* __restrict__ Wo,
    const float* __restrict__ WB, const float* __restrict__ Wdt)
{
    size_t idx = ((size_t)blockIdx.x * blockDim.x + threadIdx.x) * 2;  // (n, 2k)
    if (idx >= (size_t)NPROJ * D_) return;
    int n = (int)(idx >> 10);
    int k = (int)(idx & (D_ - 1));
    float v0, v1;
    if (n < 1024)      { v0 = Wa[(size_t)k * D_ + n];              v1 = Wa[(size_t)(k + 1) * D_ + n]; }
    else if (n < 2048) { v0 = Wo[(size_t)k * D_ + n - 1024];       v1 = Wo[(size_t)(k + 1) * D_ + n - 1024]; }
    else if (n < 4096) { v0 = WB[(size_t)k * 2048 + n - 2048];     v1 = WB[(size_t)(k + 1) * 2048 + n - 2048]; }
    else               { v0 = Wdt[(size_t)k * D_ + n - 4096];      v1 = Wdt[(size_t)(k + 1) * D_ + n - 4096]; }
    __nv_bfloat16 h0, l0, h1, l1;
    split_bf16(v0, h0, l0); split_bf16(v1, h1, l1);
    *(__nv_bfloat162*)&g_Wthi[idx] = __nv_bfloat162(h0, h1);
    *(__nv_bfloat162*)&g_Wtlo[idx] = __nv_bfloat162(l0, l1);
}

__global__ __launch_bounds__(256) void k_build_wct(const float* __restrict__ WC) {
    size_t idx = ((size_t)blockIdx.x * blockDim.x + threadIdx.x) * 2;  // [n][k], k=2048
    if (idx >= (size_t)D_ * 2 * D_) return;
    int n = (int)(idx >> 11);
    int k = (int)(idx & (2 * D_ - 1));
    float v0 = WC[(size_t)k * D_ + n];
    float v1 = WC[(size_t)(k + 1) * D_ + n];
    __nv_bfloat16 h0, l0, h1, l1;
    split_bf16(v0, h0, l0); split_bf16(v1, h1, l1);
    *(__nv_bfloat162*)&g_WCthi[idx] = __nv_bfloat162(h0, h1);
    *(__nv_bfloat162*)&g_WCtlo[idx] = __nv_bfloat162(l0, l1);
}

__global__ __launch_bounds__(256) void k_build_bias(
    const float* __restrict__ ba, const float* __restrict__ bo,
    const float* __restrict__ bB, const float* __restrict__ bdt)
{
    int n = blockIdx.x * blockDim.x + threadIdx.x;
    if (n >= NPROJ) return;
    float v;
    if (n < 1024) v = ba[n];
    else if (n < 2048) v = bo[n - 1024];
    else if (n < 4096) v = bB[n - 2048];
    else v = bdt[n - 4096];
    g_biasP[n] = v;
}

// ======================= elementwise =========================================
__device__ __forceinline__ float softplus_f(float x) {
    return fmaxf(x, 0.f) + log1pf(expf(-fabsf(x)));
}

__global__ __launch_bounds__(256) void k_elem(const float* __restrict__ x) {
    size_t idx = (size_t)blockIdx.x * blockDim.x + threadIdx.x;
    if (idx >= (size_t)M_ * D_) return;
    int d = (int)(idx & (D_ - 1));
    size_t m = idx >> 10;

    const float* Prow = g_P + m * NPROJ;
    float alpha = softplus_f(Prow[d]);
    float omega = Prow[1024 + d];
    float2 Bv   = ((const float2*)(Prow + 2048))[d];
    float dt    = softplus_f(Prow[4096 + d]);

    float xv  = x[idx];
    float tau = dt * 0.5f;
    float opa = fmaf(tau, alpha, 1.0f);
    float tw  = tau * omega;
    float inv = 1.0f / (fmaf(opa, opa, fmaf(tw, tw, EPS)));
    float m11 = opa * inv;
    float m12 = tw * inv;
    float oma = fmaf(-tau, alpha, 1.0f);

    float a = m11 * oma - m12 * tw;
    float b = m11 * tw + m12 * oma;
    float Bx0 = Bv.x * xv;
    float Bx1 = Bv.y * xv;
    float u0 = dt * (fmaf(m11, Bx0,  m12 * Bx1));
    float u1 = dt * (fmaf(-m12, Bx0, m11 * Bx1));
    g_T[idx] = make_float4(a, b, u0, u1);
}

// ======================= chunked scan ========================================
// z' = c*z + u, c = a - i b, z = h1 + i h2.
__global__ __launch_bounds__(256) void k_scan1() {
    int gid = blockIdx.x * blockDim.x + threadIdx.x;   // 0..65535
    int lane = gid & 4095;
    int ch   = gid >> 12;
    int b = lane >> 10, d = lane & (D_ - 1);
    size_t base = (size_t)b * S_ * D_ + d + (size_t)(ch * CL_) * D_;

    float Mr = 1.f, Mi = 0.f, Er = 0.f, Ei = 0.f;
#pragma unroll 4
    for (int s = 0; s < CL_; s++) {
        float4 t = g_T[base + (size_t)s * D_];
        float er = fmaf(t.x, Er, fmaf( t.y, Ei, t.z));
        float ei = fmaf(t.x, Ei, fmaf(-t.y, Er, t.w));
        float mr = fmaf(t.x, Mr,  t.y * Mi);
        float mi = fmaf(t.x, Mi, -t.y * Mr);
        Er = er; Ei = ei; Mr = mr; Mi = mi;
    }
    g_CM[gid] = make_float4(Mr, Mi, Er, Ei);
}

__global__ __launch_bounds__(256) void k_scan2(const float* __restrict__ state,
                                               float* __restrict__ out_fs) {
    int gid = blockIdx.x * blockDim.x + threadIdx.x;   // 0..4095
    float zr = state[(size_t)gid * 2 + 0];
    float zi = state[(size_t)gid * 2 + 1];
#pragma unroll
    for (int ch = 0; ch < CH_; ch++) {
        int idx = (ch << 12) | gid;
        g_HIN[idx] = make_float2(zr, zi);
        float4 me = g_CM[idx];
        float nr = fmaf(me.x, zr, fmaf(-me.y, zi, me.z));
        float ni = fmaf(me.x, zi, fmaf( me.y, zr, me.w));
        zr = nr; zi = ni;
    }
    if (out_fs) {
        out_fs[(size_t)gid * 2 + 0] = zr;
        out_fs[(size_t)gid * 2 + 1] = zi;
    }
}

__global__ __launch_bounds__(256) void k_scan3() {
    int gid = blockIdx.x * blockDim.x + threadIdx.x;   // 0..65535
    int lane = gid & 4095;
    int ch   = gid >> 12;
    int b = lane >> 10, d = lane & (D_ - 1);
    size_t base = (size_t)b * S_ * D_ + d + (size_t)(ch * CL_) * D_;

    float2 z = g_HIN[gid];
    float zr = z.x, zi = z.y;
#pragma unroll 4
    for (int s = 0; s < CL_; s++) {
        size_t i = base + (size_t)s * D_;
        float4 t = g_T[i];
        float nr = fmaf(t.x, zr, fmaf( t.y, zi, t.z));
        float ni = fmaf(t.x, zi, fmaf(-t.y, zr, t.w));
        zr = nr; zi = ni;
        size_t hoff = ((size_t)(b * S_ + ch * CL_ + s) * 2 * D_) + 2 * d;
        __nv_bfloat16 h1h, h1l, h2h, h2l;
        split_bf16(zr, h1h, h1l);
        split_bf16(zi, h2h, h2l);
        *(__nv_bfloat162*)&g_Hhi[hoff] = __nv_bfloat162(h1h, h2h);
        *(__nv_bfloat162*)&g_Hlo[hoff] = __nv_bfloat162(h1l, h2l);
    }
}

// ======================= launcher ============================================
extern "C" void kernel_launch(void* const* d_in, const int* in_sizes, int n_in,
                              void* d_out, int out_size)
{
    const float* x     = (const float*)d_in[0];
    const float* state = (const float*)d_in[1];
    const float* Wa    = (const float*)d_in[2];
    const float* ba    = (const float*)d_in[3];
    const float* Wo    = (const float*)d_in[4];
    const float* bo    = (const float*)d_in[5];
    const float* WB    = (const float*)d_in[6];
    const float* bB    = (const float*)d_in[7];
    const float* Wdt   = (const float*)d_in[8];

    const float *WC, *bC, *bdt;
    if (in_sizes[9] == 1024) {  // ..., Wdt, bdt, WC, bC
        bdt = (const float*)d_in[9];
        WC  = (const float*)d_in[10];
        bC  = (const float*)d_in[11];
    } else {                    // ..., Wdt, WC, bC, bdt
        WC  = (const float*)d_in[9];
        bC  = (const float*)d_in[10];
        bdt = (const float*)d_in[11];
    }

    float* out = (float*)d_out;
    float* out_fs = nullptr;
    if (out_size >= (int)((size_t)M_ * D_ + (size_t)B_ * D_ * 2))
        out_fs = out + (size_t)M_ * D_;

    float *pP, *pbias;
    __nv_bfloat16 *pxh, *pxl, *pwh, *pwl, *pwch, *pwcl, *phh, *phl;
    cudaGetSymbolAddress((void**)&pP,   g_P);
    cudaGetSymbolAddress((void**)&pbias,g_biasP);
    cudaGetSymbolAddress((void**)&pxh,  g_xhi);
    cudaGetSymbolAddress((void**)&pxl,  g_xlo);
    cudaGetSymbolAddress((void**)&pwh,  g_Wthi);
    cudaGetSymbolAddress((void**)&pwl,  g_Wtlo);
    cudaGetSymbolAddress((void**)&pwch, g_WCthi);
    cudaGetSymbolAddress((void**)&pwcl, g_WCtlo);
    cudaGetSymbolAddress((void**)&phh,  g_Hhi);
    cudaGetSymbolAddress((void**)&phl,  g_Hlo);

    cudaFuncSetAttribute(gemm_bf16x3, cudaFuncAttributeMaxDynamicSharedMemorySize, GEMM_SMEM);

    dim3 blk(256);

    // prep
    k_split_x  <<<(unsigned)(((size_t)M_ * D_ / 4 + 255) / 256), blk>>>(x);
    k_build_wt <<<(unsigned)(((size_t)NPROJ * D_ / 2 + 255) / 256), blk>>>(Wa, Wo, WB, Wdt);
    k_build_wct<<<(unsigned)(((size_t)D_ * 2 * D_ / 2 + 255) / 256), blk>>>(WC);
    k_build_bias<<<(NPROJ + 255) / 256, blk>>>(ba, bo, bB, bdt);

    // projections: [16384 x 1024] @ [1024 x 5120] -> g_P
    gemm_bf16x3<<<dim3(NPROJ / 128, M_ / 128), blk, GEMM_SMEM>>>(
        pxh, pxl, pwh, pwl, pbias, pP, D_, NPROJ);

    // elementwise
    k_elem<<<(unsigned)(((size_t)M_ * D_ + 255) / 256), blk>>>(x);

    // chunked scan
    k_scan1<<<(B_ * D_ * CH_) / 256, blk>>>();
    k_scan2<<<(B_ * D_) / 256, blk>>>(state, out_fs);
    k_scan3<<<(B_ * D_ * CH_) / 256, blk>>>();

    // output: [16384 x 2048] @ [2048 x 1024] -> out
    gemm_bf16x3<<<dim3(D_ / 128, M_ / 128), blk, GEMM_SMEM>>>(
        phh, phl, pwch, pwcl, bC, out, 2 * D_, D_);
}

// round 9
// speedup vs baseline: 3.0553x; 1.0385x over previous
#include <cuda_runtime.h>
#include <cuda_bf16.h>
#include <cstdint>

#define B_  4
#define S_  4096
#define D_  1024
#define M_  (B_ * S_)          // 16384 rows
#define NPROJ 5120             // 1024(a)+1024(o)+2048(B)+1024(dt)
#define EPS 1e-6f

#define CH_ 16                 // scan chunks
#define CL_ (S_ / CH_)         // 256 steps per chunk

// ---------------- scratch (static device globals; no allocation) ------------
__device__ float  g_P[(size_t)M_ * NPROJ];          // projections (335MB)
__device__ float4 g_T[(size_t)M_ * D_];             // (a,b,u0,u1) (268MB)
__device__ __nv_bfloat16 g_xhi[(size_t)M_ * D_];
__device__ __nv_bfloat16 g_xlo[(size_t)M_ * D_];
__device__ __nv_bfloat16 g_Wthi[(size_t)NPROJ * D_];   // W^T concat, [n][k]
__device__ __nv_bfloat16 g_Wtlo[(size_t)NPROJ * D_];
__device__ __nv_bfloat16 g_WCthi[(size_t)D_ * 2 * D_]; // WC^T, [n=1024][k=2048]
__device__ __nv_bfloat16 g_WCtlo[(size_t)D_ * 2 * D_];
__device__ __nv_bfloat16 g_Hhi[(size_t)M_ * 2 * D_];   // states bf16 hi [m][2d+j]
__device__ __nv_bfloat16 g_Hlo[(size_t)M_ * 2 * D_];
__device__ float  g_biasP[NPROJ];
__device__ float4 g_CM[B_ * D_ * CH_];              // per-chunk (Mr,Mi,Er,Ei)
__device__ float2 g_HIN[B_ * D_ * CH_];             // per-chunk entry state

// ======================= PTX helpers =========================================
__device__ __forceinline__ uint32_t smem_u32(const void* p) {
    uint32_t a;
    asm("{ .reg .u64 t; cvta.to.shared.u64 t, %1; cvt.u32.u64 %0, t; }" : "=r"(a) : "l"(p));
    return a;
}
__device__ __forceinline__ void cp_async16(uint32_t s, const void* g) {
    asm volatile("cp.async.cg.shared.global [%0], [%1], 16;" :: "r"(s), "l"(g));
}
#define CP_COMMIT()  asm volatile("cp.async.commit_group;" ::: "memory")
#define CP_WAIT2()   asm volatile("cp.async.wait_group 2;" ::: "memory")
#define CP_WAIT1()   asm volatile("cp.async.wait_group 1;" ::: "memory")
#define CP_WAIT0()   asm volatile("cp.async.wait_group 0;" ::: "memory")

__device__ __forceinline__ void ldsm_x4(uint32_t& r0, uint32_t& r1, uint32_t& r2,
                                        uint32_t& r3, uint32_t addr) {
    asm volatile("ldmatrix.sync.aligned.m8n8.x4.shared.b16 {%0,%1,%2,%3}, [%4];"
                 : "=r"(r0), "=r"(r1), "=r"(r2), "=r"(r3) : "r"(addr));
}
__device__ __forceinline__ void mma_bf16(float* c, const uint32_t* a, const uint32_t* b) {
    asm volatile(
        "mma.sync.aligned.m16n8k16.row.col.f32.bf16.bf16.f32 "
        "{%0,%1,%2,%3}, {%4,%5,%6,%7}, {%8,%9}, {%0,%1,%2,%3};"
        : "+f"(c[0]), "+f"(c[1]), "+f"(c[2]), "+f"(c[3])
        : "r"(a[0]), "r"(a[1]), "r"(a[2]), "r"(a[3]), "r"(b[0]), "r"(b[1]));
}

// ======================= bf16x3 GEMM (mma.sync, sm_100-safe) =================
// C[128 x 128] per CTA = A[128 x K] @ B^T where B is [N][K] row-major (= W^T).
// bf16 hi/lo split x3: Ahi*Bhi + Ahi*Blo + Alo*Bhi, fp32 accum.
// k-chunk 32, 4-stage cp.async pipeline, prefetch distance 3 (issue-early).
// Rows padded 64B->80B (ldmatrix conflict-free: 8 rows at 80B stride cover
// all 32 banks exactly once).
#define KC      32
#define ROWB    80                         // bytes per smem row (64 data + 16 pad)
#define TILE_BYTES (128 * ROWB)            // 10240
#define STAGE_BYTES (4 * TILE_BYTES)       // Ahi,Alo,Bhi,Blo = 40960
#define NSTAGE  4
#define GEMM_SMEM (NSTAGE * STAGE_BYTES)   // 163840

__global__ __launch_bounds__(256, 1) void gemm_bf16x3(
    const __nv_bfloat16* __restrict__ Ahi, const __nv_bfloat16* __restrict__ Alo,
    const __nv_bfloat16* __restrict__ Bhi, const __nv_bfloat16* __restrict__ Blo,
    const float* __restrict__ bias, float* __restrict__ C,
    int Kdim, int ldc)
{
    extern __shared__ char smem[];
    const uint32_t sbase = smem_u32(smem);

    const int tid  = threadIdx.x;
    const int wid  = tid >> 5;
    const int lane = tid & 31;
    const int bm   = blockIdx.y * 128;
    const int bn   = blockIdx.x * 128;
    const int wm   = (wid & 1) * 64;       // warp m offset
    const int wn   = (wid >> 1) * 32;      // warp n offset

    const size_t ldab = (size_t)Kdim * 2;  // bytes per row of A/B sources

    // cp.async: 8 chunks/thread/stage (2 per matrix). chunk c: row=c>>2, k16B=c&3
    const int c0 = tid, c1 = tid + 256;
    const int r0g = c0 >> 2, k0g = (c0 & 3) * 16;
    const int r1g = c1 >> 2, k1g = (c1 & 3) * 16;
    const uint32_t s0 = (uint32_t)(r0g * ROWB + k0g);
    const uint32_t s1 = (uint32_t)(r1g * ROWB + k1g);

    auto issue_stage = [&](int kc, int st) {
        const uint32_t sb = sbase + st * STAGE_BYTES;
        const size_t kbyte = (size_t)kc * (KC * 2);
        const size_t ga0 = (size_t)(bm + r0g) * ldab + kbyte + k0g;
        const size_t ga1 = (size_t)(bm + r1g) * ldab + kbyte + k1g;
        const size_t gb0 = (size_t)(bn + r0g) * ldab + kbyte + k0g;
        const size_t gb1 = (size_t)(bn + r1g) * ldab + kbyte + k1g;
        cp_async16(sb + s0,                  (const char*)Ahi + ga0);
        cp_async16(sb + s1,                  (const char*)Ahi + ga1);
        cp_async16(sb + TILE_BYTES + s0,     (const char*)Alo + ga0);
        cp_async16(sb + TILE_BYTES + s1,     (const char*)Alo + ga1);
        cp_async16(sb + 2 * TILE_BYTES + s0, (const char*)Bhi + gb0);
        cp_async16(sb + 2 * TILE_BYTES + s1, (const char*)Bhi + gb1);
        cp_async16(sb + 3 * TILE_BYTES + s0, (const char*)Blo + gb0);
        cp_async16(sb + 3 * TILE_BYTES + s1, (const char*)Blo + gb1);
        CP_COMMIT();
    };

    const int NC = Kdim / KC;
    issue_stage(0, 0);
    issue_stage(1, 1);
    issue_stage(2, 2);

    float acc[4][4][4];
#pragma unroll
    for (int mt = 0; mt < 4; mt++)
#pragma unroll
        for (int nt = 0; nt < 4; nt++)
#pragma unroll
            for (int j = 0; j < 4; j++) acc[mt][nt][j] = 0.f;

    // ldmatrix lane offsets
    const int a_m = (lane & 7) + (lane & 8);          // row within m16 tile group
    const int a_k = (lane & 16) ? 8 : 0;              // k-half
    const int b_n = (lane & 7) + ((lane & 16) ? 8 : 0);
    const int b_k = (lane & 8) ? 8 : 0;

    for (int c = 0; c < NC; c++) {
        // Ensure group for chunk c is complete. Newer pending groups after the
        // prologue+in-loop issues: 2 normally, 1 at c==NC-2, 0 at c==NC-1.
        if (c + 3 <= NC) CP_WAIT2();
        else if (c + 2 == NC) CP_WAIT1();
        else CP_WAIT0();
        __syncthreads();   // also: all warps done computing chunk c-1 (stage (c+3)&3)

        // Prefetch chunk c+3 BEFORE computing chunk c: ~3 chunks of latency cover.
        if (c + 3 < NC) issue_stage(c + 3, (c + 3) & 3);

        const int st = c & 3;
        const uint32_t sA_h = sbase + st * STAGE_BYTES;
        const uint32_t sA_l = sA_h + TILE_BYTES;
        const uint32_t sB_h = sA_h + 2 * TILE_BYTES;
        const uint32_t sB_l = sA_h + 3 * TILE_BYTES;

#pragma unroll
        for (int k16 = 0; k16 < KC / 16; k16++) {
            const int k0 = k16 * 16;
            uint32_t ah[4][4], al[4][4], bh[4][2], bl[4][2];
#pragma unroll
            for (int mt = 0; mt < 4; mt++) {
                uint32_t off = (uint32_t)((wm + mt * 16 + a_m) * ROWB + (k0 + a_k) * 2);
                ldsm_x4(ah[mt][0], ah[mt][1], ah[mt][2], ah[mt][3], sA_h + off);
                ldsm_x4(al[mt][0], al[mt][1], al[mt][2], al[mt][3], sA_l + off);
            }
#pragma unroll
            for (int np = 0; np < 2; np++) {
                uint32_t off = (uint32_t)((wn + np * 16 + b_n) * ROWB + (k0 + b_k) * 2);
                ldsm_x4(bh[2*np][0], bh[2*np][1], bh[2*np+1][0], bh[2*np+1][1], sB_h + off);
                ldsm_x4(bl[2*np][0], bl[2*np][1], bl[2*np+1][0], bl[2*np+1][1], sB_l + off);
            }
#pragma unroll
            for (int mt = 0; mt < 4; mt++)
#pragma unroll
                for (int nt = 0; nt < 4; nt++) {
                    mma_bf16(acc[mt][nt], ah[mt], bh[nt]);
                    mma_bf16(acc[mt][nt], ah[mt], bl[nt]);
                    mma_bf16(acc[mt][nt], al[mt], bh[nt]);
                }
        }
    }

    // epilogue: thread holds rows lane/4 (+8), cols 2*(lane%4) (+1) per tile
    const int er = lane >> 2;
    const int ec = (lane & 3) * 2;
#pragma unroll
    for (int mt = 0; mt < 4; mt++) {
#pragma unroll
        for (int nt = 0; nt < 4; nt++) {
            const int col = bn + wn + nt * 8 + ec;
            const float2 bv = *(const float2*)&bias[col];
            const int row0 = bm + wm + mt * 16 + er;
            float2 v0, v1;
            v0.x = acc[mt][nt][0] + bv.x;
            v0.y = acc[mt][nt][1] + bv.y;
            v1.x = acc[mt][nt][2] + bv.x;
            v1.y = acc[mt][nt][3] + bv.y;
            *(float2*)&C[(size_t)row0 * ldc + col]       = v0;
            *(float2*)&C[(size_t)(row0 + 8) * ldc + col] = v1;
        }
    }
}

// ======================= prep kernels ========================================
__device__ __forceinline__ void split_bf16(float v, __nv_bfloat16& h, __nv_bfloat16& l) {
    h = __float2bfloat16(v);
    l = __float2bfloat16(v - __bfloat162float(h));
}

__global__ __launch_bounds__(256) void k_split_x(const float* __restrict__ x) {
    size_t i4 = ((size_t)blockIdx.x * blockDim.x + threadIdx.x) * 4;
    if (i4 >= (size_t)M_ * D_) return;
    float4 v = *(const float4*)&x[i4];
    __nv_bfloat16 h0, l0, h1, l1, h2, l2, h3, l3;
    split_bf16(v.x, h0, l0); split_bf16(v.y, h1, l1);
    split_bf16(v.z, h2, l2); split_bf16(v.w, h3, l3);
    *(__nv_bfloat162*)&g_xhi[i4]     = __nv_bfloat162(h0, h1);
    *(__nv_bfloat162*)&g_xhi[i4 + 2] = __nv_bfloat162(h2, h3);
    *(__nv_bfloat162*)&g_xlo[i4]     = __nv_bfloat162(l0, l1);
    *(__nv_bfloat162*)&g_xlo[i4 + 2] = __nv_bfloat162(l2, l3);
}

// Wt_all[n][k] via 32x32 smem tile transpose (coalesced reads AND writes).
// n<1024 Wa; <2048 Wo; <4096 WB; <5120 Wdt.
__global__ __launch_bounds__(256) void k_build_wt(
    const float* __restrict__ Wa, const float* __restrict__ Wo,
    const float* __restrict__ WB, const float* __restrict__ Wdt)
{
    __shared__ float t[32][33];
    const int bn = blockIdx.x * 32;   // output n base
    const int bk = blockIdx.y * 32;   // output k base
    const int tx = threadIdx.x & 31;
    const int ty = threadIdx.x >> 5;  // 0..7

    const float* W; int ldw, noff;
    if (bn < 1024)      { W = Wa;  ldw = 1024; noff = 0; }
    else if (bn < 2048) { W = Wo;  ldw = 1024; noff = 1024; }
    else if (bn < 4096) { W = WB;  ldw = 2048; noff = 2048; }
    else                { W = Wdt; ldw = 1024; noff = 4096; }

#pragma unroll
    for (int i = 0; i < 32; i += 8)
        t[ty + i][tx] = W[(size_t)(bk + ty + i) * ldw + (bn - noff) + tx];
    __syncthreads();
#pragma unroll
    for (int i = 0; i < 32; i += 8) {
        float v = t[tx][ty + i];
        __nv_bfloat16 h, l; split_bf16(v, h, l);
        size_t o = (size_t)(bn + ty + i) * 1024 + bk + tx;
        g_Wthi[o] = h;
        g_Wtlo[o] = l;
    }
}

// WC^T[n][k], n=1024, k=2048; same tile transpose.
__global__ __launch_bounds__(256) void k_build_wct(const float* __restrict__ WC) {
    __shared__ float t[32][33];
    const int bn = blockIdx.x * 32;
    const int bk = blockIdx.y * 32;
    const int tx = threadIdx.x & 31;
    const int ty = threadIdx.x >> 5;
#pragma unroll
    for (int i = 0; i < 32; i += 8)
        t[ty + i][tx] = WC[(size_t)(bk + ty + i) * 1024 + bn + tx];
    __syncthreads();
#pragma unroll
    for (int i = 0; i < 32; i += 8) {
        float v = t[tx][ty + i];
        __nv_bfloat16 h, l; split_bf16(v, h, l);
        size_t o = (size_t)(bn + ty + i) * 2048 + bk + tx;
        g_WCthi[o] = h;
        g_WCtlo[o] = l;
    }
}

__global__ __launch_bounds__(256) void k_build_bias(
    const float* __restrict__ ba, const float* __restrict__ bo,
    const float* __restrict__ bB, const float* __restrict__ bdt)
{
    int n = blockIdx.x * blockDim.x + threadIdx.x;
    if (n >= NPROJ) return;
    float v;
    if (n < 1024) v = ba[n];
    else if (n < 2048) v = bo[n - 1024];
    else if (n < 4096) v = bB[n - 2048];
    else v = bdt[n - 4096];
    g_biasP[n] = v;
}

// ======================= elementwise =========================================
__device__ __forceinline__ float softplus_f(float x) {
    return fmaxf(x, 0.f) + log1pf(expf(-fabsf(x)));
}

__global__ __launch_bounds__(256) void k_elem(const float* __restrict__ x) {
    size_t idx = (size_t)blockIdx.x * blockDim.x + threadIdx.x;
    if (idx >= (size_t)M_ * D_) return;
    int d = (int)(idx & (D_ - 1));
    size_t m = idx >> 10;

    const float* Prow = g_P + m * NPROJ;
    float alpha = softplus_f(Prow[d]);
    float omega = Prow[1024 + d];
    float2 Bv   = ((const float2*)(Prow + 2048))[d];
    float dt    = softplus_f(Prow[4096 + d]);

    float xv  = x[idx];
    float tau = dt * 0.5f;
    float opa = fmaf(tau, alpha, 1.0f);
    float tw  = tau * omega;
    float inv = 1.0f / (fmaf(opa, opa, fmaf(tw, tw, EPS)));
    float m11 = opa * inv;
    float m12 = tw * inv;
    float oma = fmaf(-tau, alpha, 1.0f);

    float a = m11 * oma - m12 * tw;
    float b = m11 * tw + m12 * oma;
    float Bx0 = Bv.x * xv;
    float Bx1 = Bv.y * xv;
    float u0 = dt * (fmaf(m11, Bx0,  m12 * Bx1));
    float u1 = dt * (fmaf(-m12, Bx0, m11 * Bx1));
    g_T[idx] = make_float4(a, b, u0, u1);
}

// ======================= chunked scan ========================================
// z' = c*z + u, c = a - i b, z = h1 + i h2.
__global__ __launch_bounds__(256) void k_scan1() {
    int gid = blockIdx.x * blockDim.x + threadIdx.x;   // 0..65535
    int lane = gid & 4095;
    int ch   = gid >> 12;
    int b = lane >> 10, d = lane & (D_ - 1);
    size_t base = (size_t)b * S_ * D_ + d + (size_t)(ch * CL_) * D_;

    float Mr = 1.f, Mi = 0.f, Er = 0.f, Ei = 0.f;
#pragma unroll 4
    for (int s = 0; s < CL_; s++) {
        float4 t = g_T[base + (size_t)s * D_];
        float er = fmaf(t.x, Er, fmaf( t.y, Ei, t.z));
        float ei = fmaf(t.x, Ei, fmaf(-t.y, Er, t.w));
        float mr = fmaf(t.x, Mr,  t.y * Mi);
        float mi = fmaf(t.x, Mi, -t.y * Mr);
        Er = er; Ei = ei; Mr = mr; Mi = mi;
    }
    g_CM[gid] = make_float4(Mr, Mi, Er, Ei);
}

__global__ __launch_bounds__(256) void k_scan2(const float* __restrict__ state,
                                               float* __restrict__ out_fs) {
    int gid = blockIdx.x * blockDim.x + threadIdx.x;   // 0..4095
    float zr = state[(size_t)gid * 2 + 0];
    float zi = state[(size_t)gid * 2 + 1];
#pragma unroll
    for (int ch = 0; ch < CH_; ch++) {
        int idx = (ch << 12) | gid;
        g_HIN[idx] = make_float2(zr, zi);
        float4 me = g_CM[idx];
        float nr = fmaf(me.x, zr, fmaf(-me.y, zi, me.z));
        float ni = fmaf(me.x, zi, fmaf( me.y, zr, me.w));
        zr = nr; zi = ni;
    }
    if (out_fs) {
        out_fs[(size_t)gid * 2 + 0] = zr;
        out_fs[(size_t)gid * 2 + 1] = zi;
    }
}

__global__ __launch_bounds__(256) void k_scan3() {
    int gid = blockIdx.x * blockDim.x + threadIdx.x;   // 0..65535
    int lane = gid & 4095;
    int ch   = gid >> 12;
    int b = lane >> 10, d = lane & (D_ - 1);
    size_t base = (size_t)b * S_ * D_ + d + (size_t)(ch * CL_) * D_;

    float2 z = g_HIN[gid];
    float zr = z.x, zi = z.y;
#pragma unroll 4
    for (int s = 0; s < CL_; s++) {
        size_t i = base + (size_t)s * D_;
        float4 t = g_T[i];
        float nr = fmaf(t.x, zr, fmaf( t.y, zi, t.z));
        float ni = fmaf(t.x, zi, fmaf(-t.y, zr, t.w));
        zr = nr; zi = ni;
        size_t hoff = ((size_t)(b * S_ + ch * CL_ + s) * 2 * D_) + 2 * d;
        __nv_bfloat16 h1h, h1l, h2h, h2l;
        split_bf16(zr, h1h, h1l);
        split_bf16(zi, h2h, h2l);
        *(__nv_bfloat162*)&g_Hhi[hoff] = __nv_bfloat162(h1h, h2h);
        *(__nv_bfloat162*)&g_Hlo[hoff] = __nv_bfloat162(h1l, h2l);
    }
}

// ======================= launcher ============================================
extern "C" void kernel_launch(void* const* d_in, const int* in_sizes, int n_in,
                              void* d_out, int out_size)
{
    const float* x     = (const float*)d_in[0];
    const float* state = (const float*)d_in[1];
    const float* Wa    = (const float*)d_in[2];
    const float* ba    = (const float*)d_in[3];
    const float* Wo    = (const float*)d_in[4];
    const float* bo    = (const float*)d_in[5];
    const float* WB    = (const float*)d_in[6];
    const float* bB    = (const float*)d_in[7];
    const float* Wdt   = (const float*)d_in[8];

    const float *WC, *bC, *bdt;
    if (in_sizes[9] == 1024) {  // ..., Wdt, bdt, WC, bC
        bdt = (const float*)d_in[9];
        WC  = (const float*)d_in[10];
        bC  = (const float*)d_in[11];
    } else {                    // ..., Wdt, WC, bC, bdt
        WC  = (const float*)d_in[9];
        bC  = (const float*)d_in[10];
        bdt = (const float*)d_in[11];
    }

    float* out = (float*)d_out;
    float* out_fs = nullptr;
    if (out_size >= (int)((size_t)M_ * D_ + (size_t)B_ * D_ * 2))
        out_fs = out + (size_t)M_ * D_;

    float *pP, *pbias;
    __nv_bfloat16 *pxh, *pxl, *pwh, *pwl, *pwch, *pwcl, *phh, *phl;
    cudaGetSymbolAddress((void**)&pP,   g_P);
    cudaGetSymbolAddress((void**)&pbias,g_biasP);
    cudaGetSymbolAddress((void**)&pxh,  g_xhi);
    cudaGetSymbolAddress((void**)&pxl,  g_xlo);
    cudaGetSymbolAddress((void**)&pwh,  g_Wthi);
    cudaGetSymbolAddress((void**)&pwl,  g_Wtlo);
    cudaGetSymbolAddress((void**)&pwch, g_WCthi);
    cudaGetSymbolAddress((void**)&pwcl, g_WCtlo);
    cudaGetSymbolAddress((void**)&phh,  g_Hhi);
    cudaGetSymbolAddress((void**)&phl,  g_Hlo);

    cudaFuncSetAttribute(gemm_bf16x3, cudaFuncAttributeMaxDynamicSharedMemorySize, GEMM_SMEM);

    dim3 blk(256);

    // prep
    k_split_x  <<<(unsigned)(((size_t)M_ * D_ / 4 + 255) / 256), blk>>>(x);
    k_build_wt <<<dim3(NPROJ / 32, D_ / 32), blk>>>(Wa, Wo, WB, Wdt);
    k_build_wct<<<dim3(D_ / 32, 2 * D_ / 32), blk>>>(WC);
    k_build_bias<<<(NPROJ + 255) / 256, blk>>>(ba, bo, bB, bdt);

    // projections: [16384 x 1024] @ [1024 x 5120] -> g_P
    gemm_bf16x3<<<dim3(NPROJ / 128, M_ / 128), blk, GEMM_SMEM>>>(
        pxh, pxl, pwh, pwl, pbias, pP, D_, NPROJ);

    // elementwise
    k_elem<<<(unsigned)(((size_t)M_ * D_ + 255) / 256), blk>>>(x);

    // chunked scan
    k_scan1<<<(B_ * D_ * CH_) / 256, blk>>>();
    k_scan2<<<(B_ * D_) / 256, blk>>>(state, out_fs);
    k_scan3<<<(B_ * D_ * CH_) / 256, blk>>>();

    // output: [16384 x 2048] @ [2048 x 1024] -> out
    gemm_bf16x3<<<dim3(D_ / 128, M_ / 128), blk, GEMM_SMEM>>>(
        phh, phl, pwch, pwcl, bC, out, 2 * D_, D_);
}

// round 11
// speedup vs baseline: 3.7279x; 1.2202x over previous
#include <cuda_runtime.h>
#include <cuda_bf16.h>
#include <cstdint>

#define B_  4
#define S_  4096
#define D_  1024
#define M_  (B_ * S_)          // 16384 rows
#define NPROJ 5120             // 1024(a)+1024(o)+2048(B)+1024(dt)
#define EPS 1e-6f

#define CH_ 32                 // scan chunks
#define CL_ (S_ / CH_)         // 128 steps per chunk

// ---------------- scratch (static device globals; no allocation) ------------
__device__ float  g_P[(size_t)M_ * NPROJ];          // projections (335MB)
__device__ float4 g_T[(size_t)M_ * D_];             // (a,b,u0,u1) (268MB)
__device__ __nv_bfloat16 g_xhi[(size_t)M_ * D_];
__device__ __nv_bfloat16 g_xlo[(size_t)M_ * D_];
__device__ __nv_bfloat16 g_Wthi[(size_t)NPROJ * D_];   // W^T concat, [n][k]
__device__ __nv_bfloat16 g_Wtlo[(size_t)NPROJ * D_];
__device__ __nv_bfloat16 g_WCthi[(size_t)D_ * 2 * D_]; // WC^T, [n=1024][k=2048]
__device__ __nv_bfloat16 g_WCtlo[(size_t)D_ * 2 * D_];
__device__ __nv_bfloat16 g_Hhi[(size_t)M_ * 2 * D_];   // states bf16 hi [m][2d+j]
__device__ __nv_bfloat16 g_Hlo[(size_t)M_ * 2 * D_];
__device__ float  g_biasP[NPROJ];
__device__ float4 g_CM[B_ * D_ * CH_];              // per-chunk (Mr,Mi,Er,Ei)
__device__ float2 g_HIN[B_ * D_ * CH_];             // per-chunk entry state

// ======================= PTX helpers =========================================
__device__ __forceinline__ uint32_t smem_u32(const void* p) {
    uint32_t a;
    asm("{ .reg .u64 t; cvta.to.shared.u64 t, %1; cvt.u32.u64 %0, t; }" : "=r"(a) : "l"(p));
    return a;
}
__device__ __forceinline__ void cp_async16(uint32_t s, const void* g) {
    asm volatile("cp.async.cg.shared.global [%0], [%1], 16;" :: "r"(s), "l"(g));
}
#define CP_COMMIT()  asm volatile("cp.async.commit_group;" ::: "memory")
#define CP_WAIT1()   asm volatile("cp.async.wait_group 1;" ::: "memory")
#define CP_WAIT0()   asm volatile("cp.async.wait_group 0;" ::: "memory")

__device__ __forceinline__ void ldsm_x4(uint32_t& r0, uint32_t& r1, uint32_t& r2,
                                        uint32_t& r3, uint32_t addr) {
    asm volatile("ldmatrix.sync.aligned.m8n8.x4.shared.b16 {%0,%1,%2,%3}, [%4];"
                 : "=r"(r0), "=r"(r1), "=r"(r2), "=r"(r3) : "r"(addr));
}
__device__ __forceinline__ void mma_bf16(float* c, const uint32_t* a, const uint32_t* b) {
    asm volatile(
        "mma.sync.aligned.m16n8k16.row.col.f32.bf16.bf16.f32 "
        "{%0,%1,%2,%3}, {%4,%5,%6,%7}, {%8,%9}, {%0,%1,%2,%3};"
        : "+f"(c[0]), "+f"(c[1]), "+f"(c[2]), "+f"(c[3])
        : "r"(a[0]), "r"(a[1]), "r"(a[2]), "r"(a[3]), "r"(b[0]), "r"(b[1]));
}

// ======================= bf16x3 GEMM (mma.sync, sm_100-safe) =================
// C[128 x 128] per CTA = A[128 x K] @ B^T where B is [N][K] row-major (= W^T).
// bf16 hi/lo split x3: Ahi*Bhi + Ahi*Blo + Alo*Bhi, fp32 accum.
// k-chunk 32, 2-stage cp.async pipeline, 80KB smem/CTA -> 2 CTAs per SM
// (occupancy hides the per-CTA barrier/wait bubbles that capped R9 at ~58%
// of the mma.sync ceiling). launch_bounds(256,2) caps regs at 128.
#define KC      32
#define ROWB    80                         // bytes per smem row (64 data + 16 pad)
#define TILE_BYTES (128 * ROWB)            // 10240
#define STAGE_BYTES (4 * TILE_BYTES)       // Ahi,Alo,Bhi,Blo = 40960
#define NSTAGE  2
#define GEMM_SMEM (NSTAGE * STAGE_BYTES)   // 81920

__global__ __launch_bounds__(256, 2) void gemm_bf16x3(
    const __nv_bfloat16* __restrict__ Ahi, const __nv_bfloat16* __restrict__ Alo,
    const __nv_bfloat16* __restrict__ Bhi, const __nv_bfloat16* __restrict__ Blo,
    const float* __restrict__ bias, float* __restrict__ C,
    int Kdim, int ldc)
{
    extern __shared__ char smem[];
    const uint32_t sbase = smem_u32(smem);

    const int tid  = threadIdx.x;
    const int wid  = tid >> 5;
    const int lane = tid & 31;
    const int bm   = blockIdx.y * 128;
    const int bn   = blockIdx.x * 128;
    const int wm   = (wid & 1) * 64;       // warp m offset
    const int wn   = (wid >> 1) * 32;      // warp n offset

    const size_t ldab = (size_t)Kdim * 2;  // bytes per row of A/B sources

    // cp.async: 8 chunks/thread/stage (2 per matrix). chunk c: row=c>>2, k16B=c&3
    const int c0 = tid, c1 = tid + 256;
    const int r0g = c0 >> 2, k0g = (c0 & 3) * 16;
    const int r1g = c1 >> 2, k1g = (c1 & 3) * 16;
    const uint32_t s0 = (uint32_t)(r0g * ROWB + k0g);
    const uint32_t s1 = (uint32_t)(r1g * ROWB + k1g);

    auto issue_stage = [&](int kc, int st) {
        const uint32_t sb = sbase + st * STAGE_BYTES;
        const size_t kbyte = (size_t)kc * (KC * 2);
        const size_t ga0 = (size_t)(bm + r0g) * ldab + kbyte + k0g;
        const size_t ga1 = (size_t)(bm + r1g) * ldab + kbyte + k1g;
        const size_t gb0 = (size_t)(bn + r0g) * ldab + kbyte + k0g;
        const size_t gb1 = (size_t)(bn + r1g) * ldab + kbyte + k1g;
        cp_async16(sb + s0,                  (const char*)Ahi + ga0);
        cp_async16(sb + s1,                  (const char*)Ahi + ga1);
        cp_async16(sb + TILE_BYTES + s0,     (const char*)Alo + ga0);
        cp_async16(sb + TILE_BYTES + s1,     (const char*)Alo + ga1);
        cp_async16(sb + 2 * TILE_BYTES + s0, (const char*)Bhi + gb0);
        cp_async16(sb + 2 * TILE_BYTES + s1, (const char*)Bhi + gb1);
        cp_async16(sb + 3 * TILE_BYTES + s0, (const char*)Blo + gb0);
        cp_async16(sb + 3 * TILE_BYTES + s1, (const char*)Blo + gb1);
        CP_COMMIT();
    };

    const int NC = Kdim / KC;
    issue_stage(0, 0);
    issue_stage(1, 1);

    float acc[4][4][4];
#pragma unroll
    for (int mt = 0; mt < 4; mt++)
#pragma unroll
        for (int nt = 0; nt < 4; nt++)
#pragma unroll
            for (int j = 0; j < 4; j++) acc[mt][nt][j] = 0.f;

    // ldmatrix lane offsets
    const int a_m = (lane & 7) + (lane & 8);          // row within m16 tile group
    const int a_k = (lane & 16) ? 8 : 0;              // k-half
    const int b_n = (lane & 7) + ((lane & 16) ? 8 : 0);
    const int b_k = (lane & 8) ? 8 : 0;

    for (int c = 0; c < NC; c++) {
        // Group for chunk c must be complete. Outstanding newer groups: 1
        // (chunk c+1) except at the last chunk.
        if (c + 1 < NC) CP_WAIT1(); else CP_WAIT0();
        __syncthreads();

        const int st = c & 1;
        const uint32_t sA_h = sbase + st * STAGE_BYTES;
        const uint32_t sA_l = sA_h + TILE_BYTES;
        const uint32_t sB_h = sA_h + 2 * TILE_BYTES;
        const uint32_t sB_l = sA_h + 3 * TILE_BYTES;

#pragma unroll
        for (int k16 = 0; k16 < KC / 16; k16++) {
            const int k0 = k16 * 16;
            uint32_t bh[4][2], bl[4][2];
#pragma unroll
            for (int np = 0; np < 2; np++) {
                uint32_t off = (uint32_t)((wn + np * 16 + b_n) * ROWB + (k0 + b_k) * 2);
                ldsm_x4(bh[2*np][0], bh[2*np][1], bh[2*np+1][0], bh[2*np+1][1], sB_h + off);
                ldsm_x4(bl[2*np][0], bl[2*np][1], bl[2*np+1][0], bl[2*np+1][1], sB_l + off);
            }
#pragma unroll
            for (int mt = 0; mt < 4; mt++) {
                uint32_t ah[4], al[4];
                uint32_t off = (uint32_t)((wm + mt * 16 + a_m) * ROWB + (k0 + a_k) * 2);
                ldsm_x4(ah[0], ah[1], ah[2], ah[3], sA_h + off);
                ldsm_x4(al[0], al[1], al[2], al[3], sA_l + off);
#pragma unroll
                for (int nt = 0; nt < 4; nt++) {
                    mma_bf16(acc[mt][nt], ah, bh[nt]);
                    mma_bf16(acc[mt][nt], ah, bl[nt]);
                    mma_bf16(acc[mt][nt], al, bh[nt]);
                }
            }
        }
        __syncthreads();
        if (c + 2 < NC) issue_stage(c + 2, st);
    }

    // epilogue: thread holds rows lane/4 (+8), cols 2*(lane%4) (+1) per tile
    const int er = lane >> 2;
    const int ec = (lane & 3) * 2;
#pragma unroll
    for (int mt = 0; mt < 4; mt++) {
#pragma unroll
        for (int nt = 0; nt < 4; nt++) {
            const int col = bn + wn + nt * 8 + ec;
            const float2 bv = *(const float2*)&bias[col];
            const int row0 = bm + wm + mt * 16 + er;
            float2 v0, v1;
            v0.x = acc[mt][nt][0] + bv.x;
            v0.y = acc[mt][nt][1] + bv.y;
            v1.x = acc[mt][nt][2] + bv.x;
            v1.y = acc[mt][nt][3] + bv.y;
            *(float2*)&C[(size_t)row0 * ldc + col]       = v0;
            *(float2*)&C[(size_t)(row0 + 8) * ldc + col] = v1;
        }
    }
}

// ======================= prep kernels ========================================
__device__ __forceinline__ void split_bf16(float v, __nv_bfloat16& h, __nv_bfloat16& l) {
    h = __float2bfloat16(v);
    l = __float2bfloat16(v - __bfloat162float(h));
}

__global__ __launch_bounds__(256) void k_split_x(const float* __restrict__ x) {
    size_t i4 = ((size_t)blockIdx.x * blockDim.x + threadIdx.x) * 4;
    if (i4 >= (size_t)M_ * D_) return;
    float4 v = *(const float4*)&x[i4];
    __nv_bfloat16 h0, l0, h1, l1, h2, l2, h3, l3;
    split_bf16(v.x, h0, l0); split_bf16(v.y, h1, l1);
    split_bf16(v.z, h2, l2); split_bf16(v.w, h3, l3);
    *(__nv_bfloat162*)&g_xhi[i4]     = __nv_bfloat162(h0, h1);
    *(__nv_bfloat162*)&g_xhi[i4 + 2] = __nv_bfloat162(h2, h3);
    *(__nv_bfloat162*)&g_xlo[i4]     = __nv_bfloat162(l0, l1);
    *(__nv_bfloat162*)&g_xlo[i4 + 2] = __nv_bfloat162(l2, l3);
}

// Wt_all[n][k] via 32x32 smem tile transpose (coalesced reads AND writes).
// n<1024 Wa; <2048 Wo; <4096 WB; <5120 Wdt.
__global__ __launch_bounds__(256) void k_build_wt(
    const float* __restrict__ Wa, const float* __restrict__ Wo,
    const float* __restrict__ WB, const float* __restrict__ Wdt)
{
    __shared__ float t[32][33];
    const int bn = blockIdx.x * 32;   // output n base
    const int bk = blockIdx.y * 32;   // output k base
    const int tx = threadIdx.x & 31;
    const int ty = threadIdx.x >> 5;  // 0..7

    const float* W; int ldw, noff;
    if (bn < 1024)      { W = Wa;  ldw = 1024; noff = 0; }
    else if (bn < 2048) { W = Wo;  ldw = 1024; noff = 1024; }
    else if (bn < 4096) { W = WB;  ldw = 2048; noff = 2048; }
    else                { W = Wdt; ldw = 1024; noff = 4096; }

#pragma unroll
    for (int i = 0; i < 32; i += 8)
        t[ty + i][tx] = W[(size_t)(bk + ty + i) * ldw + (bn - noff) + tx];
    __syncthreads();
#pragma unroll
    for (int i = 0; i < 32; i += 8) {
        float v = t[tx][ty + i];
        __nv_bfloat16 h, l; split_bf16(v, h, l);
        size_t o = (size_t)(bn + ty + i) * 1024 + bk + tx;
        g_Wthi[o] = h;
        g_Wtlo[o] = l;
    }
}

// WC^T[n][k], n=1024, k=2048; same tile transpose.
__global__ __launch_bounds__(256) void k_build_wct(const float* __restrict__ WC) {
    __shared__ float t[32][33];
    const int bn = blockIdx.x * 32;
    const int bk = blockIdx.y * 32;
    const int tx = threadIdx.x & 31;
    const int ty = threadIdx.x >> 5;
#pragma unroll
    for (int i = 0; i < 32; i += 8)
        t[ty + i][tx] = WC[(size_t)(bk + ty + i) * 1024 + bn + tx];
    __syncthreads();
#pragma unroll
    for (int i = 0; i < 32; i += 8) {
        float v = t[tx][ty + i];
        __nv_bfloat16 h, l; split_bf16(v, h, l);
        size_t o = (size_t)(bn + ty + i) * 2048 + bk + tx;
        g_WCthi[o] = h;
        g_WCtlo[o] = l;
    }
}

__global__ __launch_bounds__(256) void k_build_bias(
    const float* __restrict__ ba, const float* __restrict__ bo,
    const float* __restrict__ bB, const float* __restrict__ bdt)
{
    int n = blockIdx.x * blockDim.x + threadIdx.x;
    if (n >= NPROJ) return;
    float v;
    if (n < 1024) v = ba[n];
    else if (n < 2048) v = bo[n - 1024];
    else if (n < 4096) v = bB[n - 2048];
    else v = bdt[n - 4096];
    g_biasP[n] = v;
}

// ======================= elementwise =========================================
__device__ __forceinline__ float softplus_f(float x) {
    return fmaxf(x, 0.f) + log1pf(expf(-fabsf(x)));
}

__global__ __launch_bounds__(256) void k_elem(const float* __restrict__ x) {
    size_t idx = (size_t)blockIdx.x * blockDim.x + threadIdx.x;
    if (idx >= (size_t)M_ * D_) return;
    int d = (int)(idx & (D_ - 1));
    size_t m = idx >> 10;

    const float* Prow = g_P + m * NPROJ;
    float alpha = softplus_f(Prow[d]);
    float omega = Prow[1024 + d];
    float2 Bv   = ((const float2*)(Prow + 2048))[d];
    float dt    = softplus_f(Prow[4096 + d]);

    float xv  = x[idx];
    float tau = dt * 0.5f;
    float opa = fmaf(tau, alpha, 1.0f);
    float tw  = tau * omega;
    float inv = 1.0f / (fmaf(opa, opa, fmaf(tw, tw, EPS)));
    float m11 = opa * inv;
    float m12 = tw * inv;
    float oma = fmaf(-tau, alpha, 1.0f);

    float a = m11 * oma - m12 * tw;
    float b = m11 * tw + m12 * oma;
    float Bx0 = Bv.x * xv;
    float Bx1 = Bv.y * xv;
    float u0 = dt * (fmaf(m11, Bx0,  m12 * Bx1));
    float u1 = dt * (fmaf(-m12, Bx0, m11 * Bx1));
    g_T[idx] = make_float4(a, b, u0, u1);
}

// ======================= chunked scan ========================================
// z' = c*z + u, c = a - i b, z = h1 + i h2.
__global__ __launch_bounds__(256) void k_scan1() {
    int gid = blockIdx.x * blockDim.x + threadIdx.x;   // 0..131071
    int lane = gid & 4095;
    int ch   = gid >> 12;
    int b = lane >> 10, d = lane & (D_ - 1);
    size_t base = (size_t)b * S_ * D_ + d + (size_t)(ch * CL_) * D_;

    float Mr = 1.f, Mi = 0.f, Er = 0.f, Ei = 0.f;
#pragma unroll 4
    for (int s = 0; s < CL_; s++) {
        float4 t = g_T[base + (size_t)s * D_];
        float er = fmaf(t.x, Er, fmaf( t.y, Ei, t.z));
        float ei = fmaf(t.x, Ei, fmaf(-t.y, Er, t.w));
        float mr = fmaf(t.x, Mr,  t.y * Mi);
        float mi = fmaf(t.x, Mi, -t.y * Mr);
        Er = er; Ei = ei; Mr = mr; Mi = mi;
    }
    g_CM[gid] = make_float4(Mr, Mi, Er, Ei);
}

__global__ __launch_bounds__(256) void k_scan2(const float* __restrict__ state,
                                               float* __restrict__ out_fs) {
    int gid = blockIdx.x * blockDim.x + threadIdx.x;   // 0..4095
    float zr = state[(size_t)gid * 2 + 0];
    float zi = state[(size_t)gid * 2 + 1];
#pragma unroll
    for (int ch = 0; ch < CH_; ch++) {
        int idx = (ch << 12) | gid;
        g_HIN[idx] = make_float2(zr, zi);
        float4 me = g_CM[idx];
        float nr = fmaf(me.x, zr, fmaf(-me.y, zi, me.z));
        float ni = fmaf(me.x, zi, fmaf( me.y, zr, me.w));
        zr = nr; zi = ni;
    }
    if (out_fs) {
        out_fs[(size_t)gid * 2 + 0] = zr;
        out_fs[(size_t)gid * 2 + 1] = zi;
    }
}

__global__ __launch_bounds__(256) void k_scan3() {
    int gid = blockIdx.x * blockDim.x + threadIdx.x;   // 0..131071
    int lane = gid & 4095;
    int ch   = gid >> 12;
    int b = lane >> 10, d = lane & (D_ - 1);
    size_t base = (size_t)b * S_ * D_ + d + (size_t)(ch * CL_) * D_;

    float2 z = g_HIN[gid];
    float zr = z.x, zi = z.y;
#pragma unroll 4
    for (int s = 0; s < CL_; s++) {
        size_t i = base + (size_t)s * D_;
        float4 t = g_T[i];
        float nr = fmaf(t.x, zr, fmaf( t.y, zi, t.z));
        float ni = fmaf(t.x, zi, fmaf(-t.y, zr, t.w));
        zr = nr; zi = ni;
        size_t hoff = ((size_t)(b * S_ + ch * CL_ + s) * 2 * D_) + 2 * d;
        __nv_bfloat16 h1h, h1l, h2h, h2l;
        split_bf16(zr, h1h, h1l);
        split_bf16(zi, h2h, h2l);
        *(__nv_bfloat162*)&g_Hhi[hoff] = __nv_bfloat162(h1h, h2h);
        *(__nv_bfloat162*)&g_Hlo[hoff] = __nv_bfloat162(h1l, h2l);
    }
}

// ======================= launcher ============================================
extern "C" void kernel_launch(void* const* d_in, const int* in_sizes, int n_in,
                              void* d_out, int out_size)
{
    const float* x     = (const float*)d_in[0];
    const float* state = (const float*)d_in[1];
    const float* Wa    = (const float*)d_in[2];
    const float* ba    = (const float*)d_in[3];
    const float* Wo    = (const float*)d_in[4];
    const float* bo    = (const float*)d_in[5];
    const float* WB    = (const float*)d_in[6];
    const float* bB    = (const float*)d_in[7];
    const float* Wdt   = (const float*)d_in[8];

    const float *WC, *bC, *bdt;
    if (in_sizes[9] == 1024) {  // ..., Wdt, bdt, WC, bC
        bdt = (const float*)d_in[9];
        WC  = (const float*)d_in[10];
        bC  = (const float*)d_in[11];
    } else {                    // ..., Wdt, WC, bC, bdt
        WC  = (const float*)d_in[9];
        bC  = (const float*)d_in[10];
        bdt = (const float*)d_in[11];
    }

    float* out = (float*)d_out;
    float* out_fs = nullptr;
    if (out_size >= (int)((size_t)M_ * D_ + (size_t)B_ * D_ * 2))
        out_fs = out + (size_t)M_ * D_;

    float *pP, *pbias;
    __nv_bfloat16 *pxh, *pxl, *pwh, *pwl, *pwch, *pwcl, *phh, *phl;
    cudaGetSymbolAddress((void**)&pP,   g_P);
    cudaGetSymbolAddress((void**)&pbias,g_biasP);
    cudaGetSymbolAddress((void**)&pxh,  g_xhi);
    cudaGetSymbolAddress((void**)&pxl,  g_xlo);
    cudaGetSymbolAddress((void**)&pwh,  g_Wthi);
    cudaGetSymbolAddress((void**)&pwl,  g_Wtlo);
    cudaGetSymbolAddress((void**)&pwch, g_WCthi);
    cudaGetSymbolAddress((void**)&pwcl, g_WCtlo);
    cudaGetSymbolAddress((void**)&phh,  g_Hhi);
    cudaGetSymbolAddress((void**)&phl,  g_Hlo);

    cudaFuncSetAttribute(gemm_bf16x3, cudaFuncAttributeMaxDynamicSharedMemorySize, GEMM_SMEM);

    dim3 blk(256);

    // prep
    k_split_x  <<<(unsigned)(((size_t)M_ * D_ / 4 + 255) / 256), blk>>>(x);
    k_build_wt <<<dim3(NPROJ / 32, D_ / 32), blk>>>(Wa, Wo, WB, Wdt);
    k_build_wct<<<dim3(D_ / 32, 2 * D_ / 32), blk>>>(WC);
    k_build_bias<<<(NPROJ + 255) / 256, blk>>>(ba, bo, bB, bdt);

    // projections: [16384 x 1024] @ [1024 x 5120] -> g_P
    gemm_bf16x3<<<dim3(NPROJ / 128, M_ / 128), blk, GEMM_SMEM>>>(
        pxh, pxl, pwh, pwl, pbias, pP, D_, NPROJ);

    // elementwise
    k_elem<<<(unsigned)(((size_t)M_ * D_ + 255) / 256), blk>>>(x);

    // chunked scan
    k_scan1<<<(B_ * D_ * CH_) / 256, blk>>>();
    k_scan2<<<(B_ * D_) / 256, blk>>>(state, out_fs);
    k_scan3<<<(B_ * D_ * CH_) / 256, blk>>>();

    // output: [16384 x 2048] @ [2048 x 1024] -> out
    gemm_bf16x3<<<dim3(D_ / 128, M_ / 128), blk, GEMM_SMEM>>>(
        phh, phl, pwch, pwcl, bC, out, 2 * D_, D_);
}